// round 17
// baseline (speedup 1.0000x reference)
#include <cuda_runtime.h>
#include <cstdint>

// SO(3) tensor product, two-phase:
//  K1 (prep): y[t][(j*NM+M)*N1+m] = sum_n cg_t[M,n,m]*x_{l2}[j,n]  (800KB scratch)
//             x1dup[l][i][m] = packed {v,v} pairs, row stride 8    (128KB scratch)
//  K2 (main): thread owns output float4 column q4 of a (i-tile,j-tile); loads its
//             y block once (LDG.128), streams rows with packed fma.f32x2 + STG.128.
//             No smem, no barriers.

#define C 512
#define NTRIPLES 23
#define NT 256
#define TI 64
#define TJ 32
#define TILES_PER_TRIPLE ((C / TI) * (C / TJ))   // 8 * 16 = 128

struct Args {
    const float* x[4];     // x_l : [C, 2l+1] row-major
    const float* cg[23];   // cg_t: [2L+1, 2l2+1, 2l1+1] row-major
    float* out;
};

// Output element offset of each triple's segment inside d_out.
__constant__ int c_off[NTRIPLES] = {
            0,  1048576,  5767168, 14942208,
       262144,  1835008,  7077888,  2621440,  8388608, 16777216,
      9699328, 18612224,   524288,  3407872, 11010048, 20447232,
      4194304, 12320768, 22282240,   786432,  4980736, 13631488, 24117248
};

// y-scratch offset per triple: 512 * cumsum(NYM), NYM = NM*N1.
__constant__ int c_yoff[NTRIPLES] = {
          0,     512,    2048,    4608,
       8192,    9728,   14336,   22016,   26624,   34304,
      45056,   52736,   63488,   66048,   73728,   86528,
     104448,  112128,  124928,  142848,  146432,  157184,  175104
};

// LPT order: triples sorted by NM descending (7,5,3,1) -> long blocks first.
__constant__ int c_perm[NTRIPLES] = {
    3, 9, 11, 15, 18, 22,        // NM=7
    2, 6, 8, 10, 14, 17, 21,     // NM=5
    1, 5, 7, 13, 16, 20,         // NM=3
    0, 4, 12, 19                 // NM=1
};

__device__ float              g_y[391 * 512];        // 800KB
__device__ unsigned long long g_x1dup[4 * 512 * 8];  // 128KB, row stride 8 (64B)

__device__ __forceinline__ void fma_f32x2(unsigned long long& d,
                                          unsigned long long a,
                                          unsigned long long b,
                                          unsigned long long c) {
    asm("fma.rn.f32x2 %0, %1, %2, %3;" : "=l"(d) : "l"(a), "l"(b), "l"(c));
}
__device__ __forceinline__ unsigned long long pack2(float lo, float hi) {
    unsigned long long r;
    asm("mov.b64 %0, {%1, %2};" : "=l"(r) : "f"(lo), "f"(hi));
    return r;
}

// ---------------- Kernel 1: prep ----------------

template<int L1, int L2, int LM>
__device__ __forceinline__ void yfill(const float* __restrict__ xg2,
                                      const float* __restrict__ cg,
                                      float* __restrict__ yout, int j0,
                                      float* s_cg)
{
    constexpr int N1 = 2 * L1 + 1;
    constexpr int N2 = 2 * L2 + 1;
    constexpr int NM = 2 * LM + 1;
    constexpr int NCG = NM * N2 * N1;

    const int tid = threadIdx.x;
    for (int k = tid; k < NCG; k += NT) s_cg[k] = cg[k];
    __syncthreads();

    const int j = j0 + tid;
    float x2r[N2];
    #pragma unroll
    for (int n = 0; n < N2; n++) x2r[n] = xg2[j * N2 + n];

    #pragma unroll
    for (int M = 0; M < NM; M++)
        #pragma unroll
        for (int m = 0; m < N1; m++) {
            float acc = 0.f;
            #pragma unroll
            for (int n = 0; n < N2; n++)
                acc = fmaf(s_cg[(M * N2 + n) * N1 + m], x2r[n], acc);
            yout[(j * NM + M) * N1 + m] = acc;
        }
}

__global__ __launch_bounds__(NT) void prep_kernel(Args a) {
    __shared__ float s_cg[343];
    const int b = blockIdx.x;

    if (b < 2 * NTRIPLES) {
        const int t  = b >> 1;
        const int j0 = (b & 1) * NT;
        float* yout = g_y + c_yoff[t];
        #define YCASE(T, A, B, L) \
            case T: yfill<A, B, L>(a.x[B], a.cg[T], yout, j0, s_cg); break;
        switch (t) {
            YCASE( 0, 0, 0, 0) YCASE( 1, 0, 1, 1) YCASE( 2, 0, 2, 2) YCASE( 3, 0, 3, 3)
            YCASE( 4, 1, 1, 0) YCASE( 5, 1, 1, 1) YCASE( 6, 1, 1, 2) YCASE( 7, 1, 2, 1)
            YCASE( 8, 1, 2, 2) YCASE( 9, 1, 2, 3) YCASE(10, 1, 3, 2) YCASE(11, 1, 3, 3)
            YCASE(12, 2, 2, 0) YCASE(13, 2, 2, 1) YCASE(14, 2, 2, 2) YCASE(15, 2, 2, 3)
            YCASE(16, 2, 3, 1) YCASE(17, 2, 3, 2) YCASE(18, 2, 3, 3) YCASE(19, 3, 3, 0)
            YCASE(20, 3, 3, 1) YCASE(21, 3, 3, 2) YCASE(22, 3, 3, 3)
        }
        #undef YCASE
    } else {
        // x1dup fill: 8192 flattened (l,i,m) entries over 2 blocks.
        const int part = b - 2 * NTRIPLES;          // 0 or 1
        for (int k = part * 4096 + threadIdx.x; k < (part + 1) * 4096; k += NT) {
            int l, i, m;
            if (k < 512)       { l = 0; i = k;            m = 0; }
            else if (k < 2048) { l = 1; i = (k - 512) / 3;  m = (k - 512) % 3; }
            else if (k < 4608) { l = 2; i = (k - 2048) / 5; m = (k - 2048) % 5; }
            else               { l = 3; i = (k - 4608) / 7; m = (k - 4608) % 7; }
            const unsigned int u = __float_as_uint(a.x[l][i * (2 * l + 1) + m]);
            g_x1dup[(l * 512 + i) * 8 + m] = ((unsigned long long)u << 32) | u;
        }
    }
}

// ---------------- Kernel 2: main ----------------

template<int L1, int L2, int LM>
__device__ __forceinline__ void tp_main(const float* __restrict__ ysrc,
                                        float* __restrict__ out,
                                        int i0, int j0)
{
    constexpr int N1 = 2 * L1 + 1;
    constexpr int NM = 2 * LM + 1;
    constexpr int G  = 8 * NM;            // float4 per i-row (TJ*NM/4)
    constexpr int RB = NT / G;            // row stride

    const int tid = threadIdx.x;
    const int q4 = tid % G;
    const int rb = tid / G;
    if (rb >= RB) return;

    // y block: N1 LDG.128 from L2-hot scratch (16B aligned; see alignment note).
    const float4* __restrict__ yp =
        (const float4*)(ysrc + (j0 * NM + q4 * 4) * N1);
    float yflat[4 * N1];
    #pragma unroll
    for (int c = 0; c < N1; c++) {
        float4 v4 = yp[c];
        yflat[4 * c + 0] = v4.x;
        yflat[4 * c + 1] = v4.y;
        yflat[4 * c + 2] = v4.z;
        yflat[4 * c + 3] = v4.w;
    }
    unsigned long long ypkA[N1], ypkB[N1];
    #pragma unroll
    for (int m = 0; m < N1; m++) {
        ypkA[m] = pack2(yflat[0 * N1 + m], yflat[1 * N1 + m]);
        ypkB[m] = pack2(yflat[2 * N1 + m], yflat[3 * N1 + m]);
    }

    float* __restrict__ op = out + ((i0 + rb) * C + j0) * NM + q4 * 4;
    const long long step = (long long)RB * C * NM;
    const unsigned long long* __restrict__ xp0 = &g_x1dup[(L1 * 512 + i0 + rb) * 8];

    #pragma unroll 2
    for (int r = rb; r < TI; r += RB) {
        unsigned long long accA = 0ull, accB = 0ull;
        #pragma unroll
        for (int mp = 0; mp < N1 / 2; mp++) {       // warp-uniform LDG.128 pairs
            const ulonglong2 xq = *(const ulonglong2*)&xp0[2 * mp];
            fma_f32x2(accA, xq.x, ypkA[2 * mp],     accA);
            fma_f32x2(accB, xq.x, ypkB[2 * mp],     accB);
            fma_f32x2(accA, xq.y, ypkA[2 * mp + 1], accA);
            fma_f32x2(accB, xq.y, ypkB[2 * mp + 1], accB);
        }
        {   // last (odd) m
            const unsigned long long xp = xp0[N1 - 1];
            fma_f32x2(accA, xp, ypkA[N1 - 1], accA);
            fma_f32x2(accB, xp, ypkB[N1 - 1], accB);
        }
        ulonglong2 v; v.x = accA; v.y = accB;
        *(ulonglong2*)op = v;                       // STG.128, 16B aligned
        op  += step;
        xp0 += RB * 8;
    }
}

__global__ __launch_bounds__(NT, 5) void tp_kernel(Args a) {
    const int t    = c_perm[blockIdx.x >> 7];   // 128 tiles per triple, LPT order
    const int tile = blockIdx.x & 127;
    const int i0 = (tile >> 4) * TI;            // 8 i-tiles
    const int j0 = (tile & 15) * TJ;            // 16 j-tiles

    float* out = a.out + c_off[t];
    const float* ysrc = g_y + c_yoff[t];

    #define CASE(T, A, B, L) \
        case T: tp_main<A, B, L>(ysrc, out, i0, j0); break;
    switch (t) {
        CASE( 0, 0, 0, 0) CASE( 1, 0, 1, 1) CASE( 2, 0, 2, 2) CASE( 3, 0, 3, 3)
        CASE( 4, 1, 1, 0) CASE( 5, 1, 1, 1) CASE( 6, 1, 1, 2) CASE( 7, 1, 2, 1)
        CASE( 8, 1, 2, 2) CASE( 9, 1, 2, 3) CASE(10, 1, 3, 2) CASE(11, 1, 3, 3)
        CASE(12, 2, 2, 0) CASE(13, 2, 2, 1) CASE(14, 2, 2, 2) CASE(15, 2, 2, 3)
        CASE(16, 2, 3, 1) CASE(17, 2, 3, 2) CASE(18, 2, 3, 3) CASE(19, 3, 3, 0)
        CASE(20, 3, 3, 1) CASE(21, 3, 3, 2) CASE(22, 3, 3, 3)
    }
    #undef CASE
}

extern "C" void kernel_launch(void* const* d_in, const int* in_sizes, int n_in,
                              void* d_out, int out_size) {
    Args a;
    for (int k = 0; k < 4; k++)  a.x[k]  = (const float*)d_in[k];
    for (int k = 0; k < 23; k++) a.cg[k] = (const float*)d_in[4 + k];
    a.out = (float*)d_out;

    prep_kernel<<<2 * NTRIPLES + 2, NT>>>(a);
    tp_kernel<<<NTRIPLES * TILES_PER_TRIPLE, NT>>>(a);
}